// round 1
// baseline (speedup 1.0000x reference)
#include <cuda_runtime.h>
#include <cuda_bf16.h>
#include <math.h>

#define BGR   32
#define NPER0 1024
#define N0    (BGR * NPER0)
#define HH    4
#define DH    32
#define HID   128
#define NE    524288
#define KK1   512
#define KK2   256
#define KK3   128
#define NC    10

// ---------------- scratch (static device memory, no allocation) ----------------
__device__ __align__(16) float g_H[N0 * HID];
__device__ __align__(16) float g_AGG[N0 * HID];
__device__ __align__(16) float g_X[N0 * HID];
__device__ __align__(16) float g_X2[N0 * HID];
__device__ float g_deg[N0];
__device__ float g_cat[N0];     // (cat @ psW) scalar per node
__device__ float g_sagg[N0];
__device__ float g_score[N0];
__device__ int   g_perm[N0];
__device__ int   g_nmap[N0];
__device__ int   g_srcA[NE], g_dstA[NE];
__device__ int   g_srcB[NE], g_dstB[NE];
__device__ float g_wA[NE], g_wB[NE];
__device__ float g_r[BGR * 2 * HID];

// ---------------- helpers ----------------
__device__ __forceinline__ void red_add_f4(float4* p, float4 v) {
    asm volatile("red.global.add.v4.f32 [%0], {%1, %2, %3, %4};"
                 :: "l"(p), "f"(v.x), "f"(v.y), "f"(v.z), "f"(v.w) : "memory");
}

// ---------------- kernels ----------------
__global__ void k_zero(float* p, int count) {
    int i = blockIdx.x * blockDim.x + threadIdx.x;
    if (i < count) p[i] = 0.f;
}

__global__ void k_deg_init(float* deg, int n) {
    int i = blockIdx.x * blockDim.x + threadIdx.x;
    if (i < n) deg[i] = 1.f;   // +1 self loop
}

__global__ void k_nmap_init(int* nmap, int n) {
    int i = blockIdx.x * blockDim.x + threadIdx.x;
    if (i < n) nmap[i] = -1;
}

__global__ void k_deg_acc(const int* __restrict__ dst, const float* __restrict__ w,
                          float* deg, int ne) {
    int e = blockIdx.x * blockDim.x + threadIdx.x;
    if (e >= ne) return;
    float wv = w ? w[e] : 1.f;
    if (wv != 0.f) atomicAdd(&deg[dst[e]], wv);
}

// per-head projection: h[n, head*32+e] = sum_d x[n, head*32+d] * W[head, d, e]
// 1 block = 128 threads (warp == head), 64 nodes per block; W column in registers.
__global__ void k_proj(const float* __restrict__ X, const float* __restrict__ W,
                       float* __restrict__ Hout, int n) {
    int t = threadIdx.x;
    int head = t >> 5, lane = t & 31;
    float wreg[32];
    #pragma unroll
    for (int d = 0; d < 32; d++) wreg[d] = W[head * 1024 + d * 32 + lane];
    int base = blockIdx.x * 64;
    int lim = min(n, base + 64);
    for (int node = base; node < lim; node++) {
        float xv = X[node * 128 + t];
        float acc = 0.f;
        #pragma unroll
        for (int d = 0; d < 32; d++)
            acc = fmaf(__shfl_sync(0xffffffffu, xv, d), wreg[d], acc);
        Hout[node * 128 + t] = acc;
    }
}

// edge-parallel normalized aggregation: one warp per edge, float4 vector atomics
__global__ void k_agg(const float* __restrict__ Hin, const int* __restrict__ src,
                      const int* __restrict__ dst, const float* __restrict__ w,
                      const float* __restrict__ deg, float* __restrict__ AGG, int ne) {
    int e = blockIdx.x * (blockDim.x >> 5) + (threadIdx.x >> 5);
    int lane = threadIdx.x & 31;
    if (e >= ne) return;
    float wv = w ? w[e] : 1.f;
    if (wv == 0.f) return;
    int s = src[e], d = dst[e];
    float coef = rsqrtf(deg[s]) * rsqrtf(deg[d]) * wv;
    float4 v = ((const float4*)(Hin + (size_t)s * 128))[lane];
    float4 o = make_float4(v.x * coef, v.y * coef, v.z * coef, v.w * coef);
    red_add_f4(((float4*)(AGG + (size_t)d * 128)) + lane, o);
}

// X = relu(AGG + H/deg + b)
__global__ void k_combine(const float* __restrict__ AGG, const float* __restrict__ Hin,
                          const float* __restrict__ b, const float* __restrict__ deg,
                          float* __restrict__ Xout, int n) {
    int i = blockIdx.x * blockDim.x + threadIdx.x;
    if (i >= n * 128) return;
    int node = i >> 7, f = i & 127;
    float v = AGG[i] + Hin[i] / deg[node] + b[f];
    Xout[i] = fmaxf(v, 0.f);
}

// per-node: att[h] = <x[h,:], A[h,:]>; catp = sum_f att[head(f)]*x[f]*psW[f]
__global__ void k_score0(const float* __restrict__ X, const float* __restrict__ A,
                         const float* __restrict__ psW, float* __restrict__ catp, int n) {
    int wid = (blockIdx.x * blockDim.x + threadIdx.x) >> 5;
    int lane = threadIdx.x & 31;
    if (wid >= n) return;
    float4 xv = ((const float4*)(X + (size_t)wid * 128))[lane];
    float4 av = ((const float4*)A)[lane];
    float att = xv.x * av.x + xv.y * av.y + xv.z * av.z + xv.w * av.w;
    // reduce within head group (8 lanes per head)
    att += __shfl_xor_sync(0xffffffffu, att, 1);
    att += __shfl_xor_sync(0xffffffffu, att, 2);
    att += __shfl_xor_sync(0xffffffffu, att, 4);
    float4 pw = ((const float4*)psW)[lane];
    float c = att * (xv.x * pw.x + xv.y * pw.y + xv.z * pw.z + xv.w * pw.w);
    #pragma unroll
    for (int o = 16; o > 0; o >>= 1) c += __shfl_xor_sync(0xffffffffu, c, o);
    if (lane == 0) catp[wid] = c;
}

__global__ void k_sagg(const float* __restrict__ catp, const int* __restrict__ src,
                       const int* __restrict__ dst, const float* __restrict__ w,
                       const float* __restrict__ deg, float* sagg, int ne) {
    int e = blockIdx.x * blockDim.x + threadIdx.x;
    if (e >= ne) return;
    float wv = w ? w[e] : 1.f;
    if (wv == 0.f) return;
    int s = src[e], d = dst[e];
    float coef = rsqrtf(deg[s]) * rsqrtf(deg[d]) * wv;
    atomicAdd(&sagg[d], catp[s] * coef);
}

__global__ void k_score_fin(const float* sagg, const float* catp, const float* deg,
                            const float* psb, float* score, int n) {
    int i = blockIdx.x * blockDim.x + threadIdx.x;
    if (i < n) score[i] = sagg[i] + catp[i] / deg[i] + psb[0];
}

// per-graph bitonic sort (descending score, tie -> lower idx), emit perm + nmap
__global__ void k_sort_topk(const float* __restrict__ score, int nper, int k,
                            int* __restrict__ perm, int* __restrict__ nmap) {
    __shared__ float sk[1024];
    __shared__ int   si[1024];
    int tid = threadIdx.x;
    int base = blockIdx.x * nper;
    for (int i = tid; i < nper; i += blockDim.x) { sk[i] = score[base + i]; si[i] = i; }
    __syncthreads();
    for (int ks = 2; ks <= nper; ks <<= 1) {
        for (int j = ks >> 1; j > 0; j >>= 1) {
            for (int i = tid; i < nper; i += blockDim.x) {
                int ixj = i ^ j;
                if (ixj > i) {
                    float ka = sk[i], kb = sk[ixj];
                    int ia = si[i], ib = si[ixj];
                    bool a_before_b = (ka > kb) || (ka == kb && ia < ib);
                    bool dirUp = ((i & ks) == 0);
                    bool sw = dirUp ? (!a_before_b) : a_before_b;
                    if (sw) { sk[i] = kb; sk[ixj] = ka; si[i] = ib; si[ixj] = ia; }
                }
            }
            __syncthreads();
        }
    }
    for (int jj = tid; jj < k; jj += blockDim.x) {
        int oldg = base + si[jj];
        int nw = blockIdx.x * k + jj;
        perm[nw] = oldg;
        nmap[oldg] = nw;
    }
}

__global__ void k_gather(const float* __restrict__ X, const float* __restrict__ score,
                         const int* __restrict__ perm, float* __restrict__ Xout) {
    int m = blockIdx.x;
    int oldg = perm[m];
    float t = tanhf(score[oldg]);
    Xout[(size_t)m * 128 + threadIdx.x] = X[(size_t)oldg * 128 + threadIdx.x] * t;
}

__global__ void k_remap(const int* __restrict__ src, const int* __restrict__ dst,
                        const float* __restrict__ w, const int* __restrict__ nmap,
                        int* srcN, int* dstN, float* wN, int ne) {
    int e = blockIdx.x * blockDim.x + threadIdx.x;
    if (e >= ne) return;
    int ns = nmap[src[e]], nd = nmap[dst[e]];
    float wv = w ? w[e] : 1.f;
    float wn = (ns >= 0 && nd >= 0) ? wv : 0.f;
    srcN[e] = ns > 0 ? ns : 0;
    dstN[e] = nd > 0 ? nd : 0;
    wN[e] = wn;
}

// per-graph max & mean readout, accumulated into r
__global__ void k_readout(const float* __restrict__ X, float* __restrict__ r, int k) {
    int g = blockIdx.x, f = threadIdx.x;
    float mx = -3.4e38f, sm = 0.f;
    const float* base = X + (size_t)g * k * 128 + f;
    for (int j = 0; j < k; j++) {
        float v = base[(size_t)j * 128];
        mx = fmaxf(mx, v);
        sm += v;
    }
    r[g * 256 + f]       += mx;
    r[g * 256 + 128 + f] += sm / (float)k;
}

__global__ void k_mlp(const float* __restrict__ r,
                      const float* __restrict__ l1W, const float* __restrict__ l1b,
                      const float* __restrict__ l2W, const float* __restrict__ l2b,
                      const float* __restrict__ l3W, const float* __restrict__ l3b,
                      float* __restrict__ out) {
    __shared__ float z0[256], z1[128], z2[64], z3[16];
    __shared__ float red2[2];
    int g = blockIdx.x, t = threadIdx.x;
    z0[t] = r[g * 256 + t];
    z0[t + 128] = r[g * 256 + 128 + t];
    __syncthreads();
    {
        float acc = l1b[t];
        for (int i = 0; i < 256; i++) acc = fmaf(z0[i], l1W[i * 128 + t], acc);
        z1[t] = fmaxf(acc, 0.f);
    }
    __syncthreads();
    if (t < 64) {
        float acc = l2b[t];
        for (int i = 0; i < 128; i++) acc = fmaf(z1[i], l2W[i * 64 + t], acc);
        z2[t] = fmaxf(acc, 0.f);
    }
    __syncthreads();
    if (t < NC) {
        float acc = l3b[t];
        for (int i = 0; i < 64; i++) acc = fmaf(z2[i], l3W[i * NC + t], acc);
        z3[t] = acc;
    }
    __syncthreads();
    if (t == 0) {
        float m = -3.4e38f;
        for (int c = 0; c < NC; c++) m = fmaxf(m, z3[c]);
        float s = 0.f;
        for (int c = 0; c < NC; c++) s += expf(z3[c] - m);
        red2[0] = m; red2[1] = logf(s);
    }
    __syncthreads();
    if (t < NC) out[g * NC + t] = z3[t] - red2[0] - red2[1];
}

// ---------------- host side ----------------
static inline int ceil_div(int a, int b) { return (a + b - 1) / b; }

struct Ptrs {
    float *H, *AGG, *X, *X2, *deg, *cat, *sagg, *score, *r;
    int *perm, *nmap, *srcA, *dstA, *srcB, *dstB;
    float *wA, *wB;
};

static void run_stage(const Ptrs& P, const float* Xin, int n, int k,
                      const int* src, const int* dst, const float* w,
                      int* srcN, int* dstN, float* wN, bool doRemap,
                      const float* W, const float* b, const float* A,
                      const float* psW, const float* psb, float* Xpooled) {
    int nper = n / BGR;
    k_proj<<<ceil_div(n, 64), 128>>>(Xin, W, P.H, n);
    k_deg_init<<<ceil_div(n, 256), 256>>>(P.deg, n);
    k_deg_acc<<<ceil_div(NE, 256), 256>>>(dst, w, P.deg, NE);
    k_zero<<<ceil_div(n * 128, 256), 256>>>(P.AGG, n * 128);
    k_agg<<<ceil_div(NE, 8), 256>>>(P.H, src, dst, w, P.deg, P.AGG, NE);
    k_combine<<<ceil_div(n * 128, 256), 256>>>(P.AGG, P.H, b, P.deg, P.X, n);
    k_score0<<<ceil_div(n * 32, 256), 256>>>(P.X, A, psW, P.cat, n);
    k_zero<<<ceil_div(n, 256), 256>>>(P.sagg, n);
    k_sagg<<<ceil_div(NE, 256), 256>>>(P.cat, src, dst, w, P.deg, P.sagg, NE);
    k_score_fin<<<ceil_div(n, 256), 256>>>(P.sagg, P.cat, P.deg, psb, P.score, n);
    k_nmap_init<<<ceil_div(n, 256), 256>>>(P.nmap, n);
    k_sort_topk<<<BGR, 512>>>(P.score, nper, k, P.perm, P.nmap);
    k_gather<<<BGR * k, 128>>>(P.X, P.score, P.perm, Xpooled);
    if (doRemap)
        k_remap<<<ceil_div(NE, 256), 256>>>(src, dst, w, P.nmap, srcN, dstN, wN, NE);
    k_readout<<<BGR, 128>>>(Xpooled, P.r, k);
}

extern "C" void kernel_launch(void* const* d_in, const int* in_sizes, int n_in,
                              void* d_out, int out_size) {
    const float* x   = (const float*)d_in[0];
    const int*   src = (const int*)d_in[1];
    const int*   dst = (const int*)d_in[2];
    const float* W1 = (const float*)d_in[3];
    const float* b1 = (const float*)d_in[4];
    const float* A1 = (const float*)d_in[5];
    const float* ps1W = (const float*)d_in[6];
    const float* ps1b = (const float*)d_in[7];
    const float* W2 = (const float*)d_in[8];
    const float* b2 = (const float*)d_in[9];
    const float* A2 = (const float*)d_in[10];
    const float* ps2W = (const float*)d_in[11];
    const float* ps2b = (const float*)d_in[12];
    const float* W3 = (const float*)d_in[13];
    const float* b3 = (const float*)d_in[14];
    const float* A3 = (const float*)d_in[15];
    const float* ps3W = (const float*)d_in[16];
    const float* ps3b = (const float*)d_in[17];
    const float* l1W = (const float*)d_in[18];
    const float* l1b = (const float*)d_in[19];
    const float* l2W = (const float*)d_in[20];
    const float* l2b = (const float*)d_in[21];
    const float* l3W = (const float*)d_in[22];
    const float* l3b = (const float*)d_in[23];
    float* out = (float*)d_out;

    Ptrs P;
    cudaGetSymbolAddress((void**)&P.H, g_H);
    cudaGetSymbolAddress((void**)&P.AGG, g_AGG);
    cudaGetSymbolAddress((void**)&P.X, g_X);
    cudaGetSymbolAddress((void**)&P.X2, g_X2);
    cudaGetSymbolAddress((void**)&P.deg, g_deg);
    cudaGetSymbolAddress((void**)&P.cat, g_cat);
    cudaGetSymbolAddress((void**)&P.sagg, g_sagg);
    cudaGetSymbolAddress((void**)&P.score, g_score);
    cudaGetSymbolAddress((void**)&P.r, g_r);
    cudaGetSymbolAddress((void**)&P.perm, g_perm);
    cudaGetSymbolAddress((void**)&P.nmap, g_nmap);
    cudaGetSymbolAddress((void**)&P.srcA, g_srcA);
    cudaGetSymbolAddress((void**)&P.dstA, g_dstA);
    cudaGetSymbolAddress((void**)&P.srcB, g_srcB);
    cudaGetSymbolAddress((void**)&P.dstB, g_dstB);
    cudaGetSymbolAddress((void**)&P.wA, g_wA);
    cudaGetSymbolAddress((void**)&P.wB, g_wB);

    k_zero<<<ceil_div(BGR * 256, 256), 256>>>(P.r, BGR * 256);

    // stage 1: n = N0, edges from inputs (w == 1)
    run_stage(P, x, N0, KK1, src, dst, nullptr,
              P.srcA, P.dstA, P.wA, true,
              W1, b1, A1, ps1W, ps1b, P.X2);
    // stage 2: n = B*K1, edges A -> B
    run_stage(P, P.X2, BGR * KK1, KK2, P.srcA, P.dstA, P.wA,
              P.srcB, P.dstB, P.wB, true,
              W2, b2, A2, ps2W, ps2b, P.X2);
    // stage 3: n = B*K2, edges B (no remap needed after)
    run_stage(P, P.X2, BGR * KK2, KK3, P.srcB, P.dstB, P.wB,
              nullptr, nullptr, nullptr, false,
              W3, b3, A3, ps3W, ps3b, P.X2);

    k_mlp<<<BGR, 128>>>(P.r, l1W, l1b, l2W, l2b, l3W, l3b, out);
}